// round 11
// baseline (speedup 1.0000x reference)
#include <cuda_runtime.h>
#include <math.h>
#include <float.h>
#include <stdint.h>

// Problem constants
#define Bn 32
#define Mn 384
#define Nn 128
#define Cn 92

static __device__ __constant__ float kCOST_IOU = 2.0f;
static __device__ __constant__ float kCOST_L1  = 5.0f;
static __device__ __constant__ float kCOST_CAT = 1.0f;
static __device__ __constant__ float kEPS      = 1e-7f;

// Scratch (device globals: allocation-free)
__device__ float  g_cost[(size_t)Bn * Nn * Mn];   // [b][n][m]
__device__ float2 g_stats[Bn * Mn];               // (max, sumexp) per (b,m)
__device__ float4 g_pxy[Bn * Mn];                 // pred xyxy
__device__ float4 g_txy[Bn * Nn];                 // targ xyxy
__device__ int    g_assign[Bn * Nn];
__device__ float  g_loss[Bn];
__device__ int    g_done;

// GIoU-loss + L1 helper (matches reference formula order)
__device__ __forceinline__ float bbox_pair_cost(float4 p, float4 t) {
    float ix1 = fmaxf(p.x, t.x), iy1 = fmaxf(p.y, t.y);
    float ix2 = fminf(p.z, t.z), iy2 = fminf(p.w, t.w);
    float inter = fmaxf(ix2 - ix1, 0.0f) * fmaxf(iy2 - iy1, 0.0f);
    float ap = (p.z - p.x) * (p.w - p.y);
    float at = (t.z - t.x) * (t.w - t.y);
    float un = ap + at - inter;
    float iou = inter / (un + kEPS);
    float cx1 = fminf(p.x, t.x), cy1 = fminf(p.y, t.y);
    float cx2 = fmaxf(p.z, t.z), cy2 = fmaxf(p.w, t.w);
    float ac = (cx2 - cx1) * (cy2 - cy1);
    float giou = iou - (ac - un) / (ac + kEPS);
    float gl = 1.0f - giou;
    float l1 = (fabsf(p.x - t.x) + fabsf(p.y - t.y) +
                fabsf(p.z - t.z) + fabsf(p.w - t.w)) * 0.25f;
    return kCOST_IOU * gl + kCOST_L1 * l1;
}

// ---------------------------------------------------------------------------
// Kernel 1 (fused prep + cost): block per batch, 384 threads, thread = m.
// Zero dynamic smem -> full L1 for the per-thread pred_cat rows (141 KB/block,
// resident across the 128 n-iterations). Identical arithmetic op order.
// ---------------------------------------------------------------------------
__global__ __launch_bounds__(Mn) void prep_cost_kernel(
        const float* __restrict__ pred_cat,
        const float* __restrict__ pred_bbox,
        const int*   __restrict__ targ_cat,
        const float* __restrict__ targ_bbox) {
    int b = blockIdx.x, m = threadIdx.x;
    __shared__ float4 txy_sh[Nn];
    __shared__ int    tcs_sh[Nn];

    if (b == 0 && m == 0) g_done = 0;            // reset ticket each replay

    int t = b * Mn + m;
    const float* myrow = pred_cat + (size_t)t * Cn;

    // softmax stats (float4 loads, scalar op order preserved)
    float mx = -FLT_MAX;
    {
        const float4* r4 = (const float4*)myrow;
        #pragma unroll
        for (int q = 0; q < Cn / 4; q++) {
            float4 v = r4[q];
            mx = fmaxf(mx, v.x); mx = fmaxf(mx, v.y);
            mx = fmaxf(mx, v.z); mx = fmaxf(mx, v.w);
        }
    }
    float s = 0.0f;
    {
        const float4* r4 = (const float4*)myrow;
        #pragma unroll
        for (int q = 0; q < Cn / 4; q++) {
            float4 v = r4[q];
            s += expf(v.x - mx); s += expf(v.y - mx);
            s += expf(v.z - mx); s += expf(v.w - mx);
        }
    }
    g_stats[t] = make_float2(mx, s);

    float4 myp;
    {
        const float* pb = pred_bbox + (size_t)t * 4;
        float cx = pb[0], cy = pb[1], w = pb[2], h = pb[3];
        myp = make_float4(cx - 0.5f * w, cy - 0.5f * h,
                          cx + 0.5f * w, cy + 0.5f * h);
        g_pxy[t] = myp;
    }
    if (m < Nn) {
        const float* tb = targ_bbox + ((size_t)(b * Nn + m)) * 4;
        float cx = tb[0], cy = tb[1], w = tb[2], h = tb[3];
        float4 tv = make_float4(cx - 0.5f * w, cy - 0.5f * h,
                                cx + 0.5f * w, cy + 0.5f * h);
        txy_sh[m] = tv;
        g_txy[b * Nn + m] = tv;
        tcs_sh[m] = targ_cat[b * Nn + m];
    }
    __syncthreads();

    // cost rows: identical formula order to the separate cost_kernel
    float* gcb = g_cost + (size_t)b * Nn * Mn;
    for (int n = 0; n < Nn; n++) {
        int tc = tcs_sh[n];
        float4 t4 = txy_sh[n];
        float maskf = (tc != 0) ? 1.0f : 0.0f;
        float logit = myrow[tc];                 // L1-resident after n=0
        float prob = expf(logit - mx) / s;
        float cat = kCOST_CAT * (1.0f - prob);
        float bb = bbox_pair_cost(myp, t4);
        gcb[n * Mn + m] = cat + bb * maskf;      // coalesced
    }
}

// ---------------------------------------------------------------------------
// Kernel 2: Hungarian (JV) — block-per-batch, 384 threads, 1 col/thread.
// R10 solver + depth-4 TREE block-stage scan (was 11-deep sequential).
// f64 duals, numpy op order, exact lowest-index tie-break via u64 keys.
// ---------------------------------------------------------------------------
#define CS_BYTES   (Nn * Mn * 4)             // 196608
#define OFF_U      (CS_BYTES)                // double[Nn+1]
#define OFF_P      (OFF_U + (Nn + 1) * 8)    // int[Mn+1]
#define OFF_WAY    (OFF_P + (Mn + 1) * 4)    // int[Mn+1]
#define SMEM_TOTAL (OFF_WAY + (Mn + 1) * 4)  // ~200 KB dynamic

__device__ __forceinline__ unsigned long long dkey(double d) {
    unsigned long long b = (unsigned long long)__double_as_longlong(d);
    return (b & 0x8000000000000000ull) ? ~b : (b | 0x8000000000000000ull);
}
__device__ __forceinline__ double dunkey(unsigned long long k) {
    unsigned long long b = (k & 0x8000000000000000ull)
                         ? (k & 0x7FFFFFFFFFFFFFFFull) : ~k;
    return __longlong_as_double((long long)b);
}

// lexicographic (key, idx) min into (ka,ia,pa) — associative, preserves
// lowest-index tie-break in any reduction shape
#define RMIN3(ka,ia,pa, kb,ib,pb) \
    do { if ((kb) < (ka) || ((kb) == (ka) && (ib) < (ia))) { \
        (ka) = (kb); (ia) = (ib); (pa) = (pb); } } while (0)

__global__ __launch_bounds__(Mn, 1) void hungarian_kernel(
        const float* __restrict__ pred_cat,
        const int* __restrict__ targ_cat,
        float* __restrict__ out, int mode) {
    const unsigned FULL = 0xffffffffu;
    int b = blockIdx.x;
    extern __shared__ unsigned char smem[];
    float*  cs   = (float*)smem;
    double* u_sh = (double*)(smem + OFF_U);
    int*    p_sh = (int*)(smem + OFF_P);
    int*    way  = (int*)(smem + OFF_WAY);

    __shared__ unsigned long long wkey[2][12];
    __shared__ int widx[2][12];
    __shared__ int wpv [2][12];
    __shared__ int   a_sh[Nn];
    __shared__ float r1[4], r2[4], r3[4];
    __shared__ int   ticket;

    int tid = threadIdx.x;
    int wid = tid >> 5, lane = tid & 31;
    const int mycol = tid + 1;
    const double DINF = (double)INFINITY;

    // ---- stage cost tile into smem (float4) ----
    {
        const float4* gc = (const float4*)(g_cost + (size_t)b * Nn * Mn);
        float4* c4 = (float4*)cs;
        #pragma unroll 4
        for (int idx = tid; idx < Nn * Mn / 4; idx += Mn) c4[idx] = gc[idx];
    }
    p_sh[mycol] = 0;
    if (tid <= Nn) u_sh[tid] = 0.0;
    __syncthreads();

    double v_reg = 0.0, minv;
    bool used;
    int my_p;
    int parity = 0;

    for (int i = 1; i <= Nn; i++) {
        minv = DINF;
        used = false;
        my_p = p_sh[mycol];              // stable during the path
        int j0 = 0;
        // hoisted first op of numpy's (cost - u) - v for row i
        double pre = (double)cs[(i - 1) * Mn + tid] - u_sh[i];

        while (true) {
            unsigned long long key;
            if (!used) {
                double cur = pre - v_reg;
                if (cur < minv) { minv = cur; way[mycol] = j0; }
                key = dkey(minv);
            } else {
                key = 0xFFFFFFFFFFFFFFFFull;
            }
            unsigned fk = (unsigned)(key >> 32);   // monotone top-32 of key
            int idx = mycol;
            int pv  = my_p;

            // warp stage: REDUX fast path; exact (u64,idx,pv) chain on ties
            unsigned rmin = __reduce_min_sync(FULL, fk);
            unsigned bal  = __ballot_sync(FULL, fk == rmin);
            if (__popc(bal) == 1) {
                int w = __ffs(bal) - 1;
                key = __shfl_sync(FULL, key, w);
                idx = __shfl_sync(FULL, idx, w);
                pv  = __shfl_sync(FULL, pv,  w);
            } else {
                #pragma unroll
                for (int off = 16; off; off >>= 1) {
                    unsigned long long ok = __shfl_down_sync(FULL, key, off);
                    int                oi = __shfl_down_sync(FULL, idx, off);
                    int                op = __shfl_down_sync(FULL, pv,  off);
                    if (ok < key || (ok == key && oi < idx)) {
                        key = ok; idx = oi; pv = op;
                    }
                }
                key = __shfl_sync(FULL, key, 0);
                idx = __shfl_sync(FULL, idx, 0);
                pv  = __shfl_sync(FULL, pv,  0);
            }
            if (lane == 0) {
                wkey[parity][wid] = key;
                widx[parity][wid] = idx;
                wpv [parity][wid] = pv;
            }
            __syncthreads();                      // the ONLY barrier per step

            // block stage: depth-4 TREE over 12 records (broadcast LDS)
            unsigned long long tk0 = wkey[parity][0],  tk1 = wkey[parity][1];
            unsigned long long tk2 = wkey[parity][2],  tk3 = wkey[parity][3];
            unsigned long long tk4 = wkey[parity][4],  tk5 = wkey[parity][5];
            unsigned long long tk6 = wkey[parity][6],  tk7 = wkey[parity][7];
            unsigned long long tk8 = wkey[parity][8],  tk9 = wkey[parity][9];
            unsigned long long tka = wkey[parity][10], tkb = wkey[parity][11];
            int ti0 = widx[parity][0],  ti1 = widx[parity][1];
            int ti2 = widx[parity][2],  ti3 = widx[parity][3];
            int ti4 = widx[parity][4],  ti5 = widx[parity][5];
            int ti6 = widx[parity][6],  ti7 = widx[parity][7];
            int ti8 = widx[parity][8],  ti9 = widx[parity][9];
            int tia = widx[parity][10], tib = widx[parity][11];
            int tp0 = wpv[parity][0],  tp1 = wpv[parity][1];
            int tp2 = wpv[parity][2],  tp3 = wpv[parity][3];
            int tp4 = wpv[parity][4],  tp5 = wpv[parity][5];
            int tp6 = wpv[parity][6],  tp7 = wpv[parity][7];
            int tp8 = wpv[parity][8],  tp9 = wpv[parity][9];
            int tpa = wpv[parity][10], tpb = wpv[parity][11];
            // level 1 (6 independent)
            RMIN3(tk0,ti0,tp0, tk1,ti1,tp1);
            RMIN3(tk2,ti2,tp2, tk3,ti3,tp3);
            RMIN3(tk4,ti4,tp4, tk5,ti5,tp5);
            RMIN3(tk6,ti6,tp6, tk7,ti7,tp7);
            RMIN3(tk8,ti8,tp8, tk9,ti9,tp9);
            RMIN3(tka,tia,tpa, tkb,tib,tpb);
            // level 2 (3 independent)
            RMIN3(tk0,ti0,tp0, tk2,ti2,tp2);
            RMIN3(tk4,ti4,tp4, tk6,ti6,tp6);
            RMIN3(tk8,ti8,tp8, tka,tia,tpa);
            // level 3 + 4
            RMIN3(tk0,ti0,tp0, tk4,ti4,tp4);
            RMIN3(tk0,ti0,tp0, tk8,ti8,tp8);

            double delta = dunkey(tk0);           // exact f64 minv[k]
            int k = ti0, k_p = tp0;

            // prefetch NEXT step's row + u and hoist the first subtraction.
            // Safe: rows updated below (rows of used cols + row i) are all
            // distinct from k_p (row matched to the still-free column k).
            int rowbase = (k_p > 0) ? (k_p - 1) * Mn : 0;
            float  c_next = cs[rowbase + tid];
            double u_next = u_sh[(k_p > 0) ? k_p : 0];
            double pre_next = (double)c_next - u_next;   // overlaps updates

            // dual updates (numpy f64 op order; rows disjoint across threads)
            if (used) {
                v_reg -= delta;
                u_sh[my_p] += delta;
            } else {
                minv -= delta;
            }
            if (tid == 0) u_sh[i] += delta;       // virtual column 0 (p[0]=i)

            // numpy marks used[j0] at next-iteration top == mark k here
            if (mycol == k) used = true;

            parity ^= 1;
            j0 = k; pre = pre_next;
            if (k_p == 0) break;
        }

        // augment along alternating path (thread 0; way[] visible via BAR)
        if (tid == 0) {
            int jj = j0;
            while (jj) {
                int j1 = way[jj];
                p_sh[jj] = (j1 == 0) ? i : p_sh[j1];
                jj = j1;
            }
        }
        __syncthreads();
    }

    // ---- write assignment (direct to out for mode 0) + inverse map ----
    {
        int pi = p_sh[mycol];
        if (pi > 0) {
            int a = mycol - 1;
            g_assign[b * Nn + (pi - 1)] = a;
            a_sh[pi - 1] = a;
            if (mode == 0)      out[1 + b * Nn + (pi - 1)] = (float)a;
            else if (mode == 1) out[b * Nn + (pi - 1)]     = (float)a;
        }
    }
    __syncthreads();

    // ---- fused per-batch loss ----
    float s_ce = 0.0f, s_bl = 0.0f, s_mk = 0.0f;
    if (tid < Nn) {
        int n  = tid;
        int a  = a_sh[n];
        int tc = targ_cat[b * Nn + n];
        float2 st = g_stats[b * Mn + a];
        float logit = pred_cat[((size_t)(b * Mn + a)) * Cn + tc];
        s_ce = -(logit - st.x - logf(st.y));
        float bl = bbox_pair_cost(g_pxy[b * Mn + a], g_txy[b * Nn + n]);
        s_mk = (tc != 0) ? 1.0f : 0.0f;
        s_bl = bl * s_mk;
    }
    #pragma unroll
    for (int off = 16; off; off >>= 1) {
        s_ce += __shfl_down_sync(FULL, s_ce, off);
        s_bl += __shfl_down_sync(FULL, s_bl, off);
        s_mk += __shfl_down_sync(FULL, s_mk, off);
    }
    if (wid < 4 && lane == 0) { r1[wid] = s_ce; r2[wid] = s_bl; r3[wid] = s_mk; }
    __syncthreads();
    if (tid == 0) {
        float ce_sum = r1[0] + r1[1] + r1[2] + r1[3];
        float bl_sum = r2[0] + r2[1] + r2[2] + r2[3];
        float mk_sum = r3[0] + r3[1] + r3[2] + r3[3];
        g_loss[b] = (ce_sum / (float)Nn) + bl_sum / (mk_sum + kEPS);
        __threadfence();
        ticket = atomicAdd(&g_done, 1);
    }
    __syncthreads();

    // last-arriving block reduces the 32 losses (fixed order: deterministic)
    if (tid == 0 && ticket == Bn - 1 && (mode == 0 || mode == 2)) {
        __threadfence();
        float s = 0.0f;
        for (int bb = 0; bb < Bn; bb++) s += g_loss[bb];
        out[0] = s / (float)Bn;
    }
}

// ---------------------------------------------------------------------------
// Finalize (only for fallback modes; mode 0 handled in-solver)
// ---------------------------------------------------------------------------
__global__ void finalize_kernel(float* __restrict__ out, int mode) {
    int t = blockIdx.x * blockDim.x + threadIdx.x;
    if (mode == 1) {
        if (t < Bn * Nn) out[t] = (float)g_assign[t];
    } else {
        if (t == 0) {
            float s = 0.0f;
            for (int b = 0; b < Bn; b++) s += g_loss[b];
            out[0] = s / (float)Bn;
        }
    }
}

// ---------------------------------------------------------------------------
extern "C" void kernel_launch(void* const* d_in, const int* in_sizes, int n_in,
                              void* d_out, int out_size) {
    const float* pred_cat  = (const float*)d_in[0];
    const float* pred_bbox = (const float*)d_in[1];
    const int*   targ_cat  = (const int*)d_in[2];
    const float* targ_bbox = (const float*)d_in[3];
    float* out = (float*)d_out;

    int mode;
    if (out_size == Bn * Nn + 1)      mode = 0;
    else if (out_size == Bn * Nn)     mode = 1;
    else                              mode = 2;

    prep_cost_kernel<<<Bn, Mn>>>(pred_cat, pred_bbox, targ_cat, targ_bbox);

    cudaFuncSetAttribute(hungarian_kernel,
                         cudaFuncAttributeMaxDynamicSharedMemorySize, SMEM_TOTAL);
    hungarian_kernel<<<Bn, Mn, SMEM_TOTAL>>>(pred_cat, targ_cat, out, mode);

    if (mode != 0)
        finalize_kernel<<<(Bn * Nn + 127) / 128, 128>>>(out, mode);
}

// round 13
// speedup vs baseline: 1.6017x; 1.6017x over previous
#include <cuda_runtime.h>
#include <math.h>
#include <float.h>
#include <stdint.h>

// Problem constants
#define Bn 32
#define Mn 384
#define Nn 128
#define Cn 92

static __device__ __constant__ float kCOST_IOU = 2.0f;
static __device__ __constant__ float kCOST_L1  = 5.0f;
static __device__ __constant__ float kCOST_CAT = 1.0f;
static __device__ __constant__ float kEPS      = 1e-7f;

// Scratch (device globals: allocation-free)
__device__ float  g_cost[(size_t)Bn * Nn * Mn];   // [b][n][m]
__device__ float2 g_stats[Bn * Mn];               // (max, sumexp) per (b,m)
__device__ float4 g_pxy[Bn * Mn];                 // pred xyxy
__device__ float4 g_txy[Bn * Nn];                 // targ xyxy
__device__ int    g_assign[Bn * Nn];
__device__ float  g_loss[Bn];
__device__ int    g_done;

// ---------------------------------------------------------------------------
// Kernel 1: per-(b,m) softmax stats + pred xyxy; per-(b,n) targ xyxy
// ---------------------------------------------------------------------------
__global__ void prep_kernel(const float* __restrict__ pred_cat,
                            const float* __restrict__ pred_bbox,
                            const float* __restrict__ targ_bbox) {
    int t = blockIdx.x * blockDim.x + threadIdx.x;
    if (t == 0) g_done = 0;                      // reset ticket each replay
    if (t < Bn * Mn) {
        const float4* r4 = (const float4*)(pred_cat + (size_t)t * Cn);
        float mx = -FLT_MAX;
        #pragma unroll
        for (int q = 0; q < Cn / 4; q++) {
            float4 v = r4[q];
            mx = fmaxf(mx, v.x); mx = fmaxf(mx, v.y);
            mx = fmaxf(mx, v.z); mx = fmaxf(mx, v.w);
        }
        float s = 0.0f;
        #pragma unroll
        for (int q = 0; q < Cn / 4; q++) {
            float4 v = r4[q];
            s += expf(v.x - mx); s += expf(v.y - mx);
            s += expf(v.z - mx); s += expf(v.w - mx);
        }
        g_stats[t] = make_float2(mx, s);
        const float* pb = pred_bbox + (size_t)t * 4;
        float cx = pb[0], cy = pb[1], w = pb[2], h = pb[3];
        g_pxy[t] = make_float4(cx - 0.5f * w, cy - 0.5f * h,
                               cx + 0.5f * w, cy + 0.5f * h);
    } else if (t < Bn * Mn + Bn * Nn) {
        int u = t - Bn * Mn;
        float cx = targ_bbox[u * 4 + 0], cy = targ_bbox[u * 4 + 1];
        float w  = targ_bbox[u * 4 + 2], h  = targ_bbox[u * 4 + 3];
        g_txy[u] = make_float4(cx - 0.5f * w, cy - 0.5f * h,
                               cx + 0.5f * w, cy + 0.5f * h);
    }
}

// GIoU-loss + L1 helper (matches reference formula order)
__device__ __forceinline__ float bbox_pair_cost(float4 p, float4 t) {
    float ix1 = fmaxf(p.x, t.x), iy1 = fmaxf(p.y, t.y);
    float ix2 = fminf(p.z, t.z), iy2 = fminf(p.w, t.w);
    float inter = fmaxf(ix2 - ix1, 0.0f) * fmaxf(iy2 - iy1, 0.0f);
    float ap = (p.z - p.x) * (p.w - p.y);
    float at = (t.z - t.x) * (t.w - t.y);
    float un = ap + at - inter;
    float iou = inter / (un + kEPS);
    float cx1 = fminf(p.x, t.x), cy1 = fminf(p.y, t.y);
    float cx2 = fmaxf(p.z, t.z), cy2 = fmaxf(p.w, t.w);
    float ac = (cx2 - cx1) * (cy2 - cy1);
    float giou = iou - (ac - un) / (ac + kEPS);
    float gl = 1.0f - giou;
    float l1 = (fabsf(p.x - t.x) + fabsf(p.y - t.y) +
                fabsf(p.z - t.z) + fabsf(p.w - t.w)) * 0.25f;
    return kCOST_IOU * gl + kCOST_L1 * l1;
}

// ---------------------------------------------------------------------------
// Kernel 2: cost matrix, one block per (b,n), thread per m (coalesced writes)
// ---------------------------------------------------------------------------
__global__ __launch_bounds__(Mn) void cost_kernel(const float* __restrict__ pred_cat,
                                                  const int* __restrict__ targ_cat) {
    int b = blockIdx.y, n = blockIdx.x, m = threadIdx.x;
    int tc = targ_cat[b * Nn + n];
    float4 t4 = g_txy[b * Nn + n];
    float maskf = (tc != 0) ? 1.0f : 0.0f;

    float2 st = g_stats[b * Mn + m];
    float logit = pred_cat[((size_t)(b * Mn + m)) * Cn + tc];
    float prob = expf(logit - st.x) / st.y;
    float cat = kCOST_CAT * (1.0f - prob);

    float bb = bbox_pair_cost(g_pxy[b * Mn + m], t4);
    g_cost[((size_t)(b * Nn + n)) * Mn + m] = cat + bb * maskf;
}

// ---------------------------------------------------------------------------
// Kernel 3: Hungarian (JV) — block-per-batch, 384 threads, 1 col/thread.
// Issue-bound solver: the 12-record block scan runs in WARP 0 ONLY (shfl
// tree); all other threads re-read one packed record after a 2nd barrier.
// f64 duals, numpy op order, exact lowest-index tie-break via u64 keys.
// ---------------------------------------------------------------------------
#define CS_BYTES   (Nn * Mn * 4)             // 196608
#define OFF_U      (CS_BYTES)                // double[Nn+1]
#define OFF_P      (OFF_U + (Nn + 1) * 8)    // int[Mn+1]
#define OFF_WAY    (OFF_P + (Mn + 1) * 4)    // int[Mn+1]
#define SMEM_TOTAL (OFF_WAY + (Mn + 1) * 4)  // ~200 KB dynamic

__device__ __forceinline__ unsigned long long dkey(double d) {
    unsigned long long b = (unsigned long long)__double_as_longlong(d);
    return (b & 0x8000000000000000ull) ? ~b : (b | 0x8000000000000000ull);
}
__device__ __forceinline__ double dunkey(unsigned long long k) {
    unsigned long long b = (k & 0x8000000000000000ull)
                         ? (k & 0x7FFFFFFFFFFFFFFFull) : ~k;
    return __longlong_as_double((long long)b);
}

__global__ __launch_bounds__(Mn, 1) void hungarian_kernel(
        const float* __restrict__ pred_cat,
        const int* __restrict__ targ_cat,
        float* __restrict__ out, int mode) {
    const unsigned FULL = 0xffffffffu;
    int b = blockIdx.x;
    extern __shared__ unsigned char smem[];
    float*  cs   = (float*)smem;
    double* u_sh = (double*)(smem + OFF_U);
    int*    p_sh = (int*)(smem + OFF_P);
    int*    way  = (int*)(smem + OFF_WAY);

    __shared__ unsigned long long wkey[12];
    __shared__ int widx[12];
    __shared__ int wpv [12];
    __shared__ ulonglong2 finrec;        // {delta_bits, k<<32|k_p}
    __shared__ int   a_sh[Nn];
    __shared__ float r1[4], r2[4], r3[4];
    __shared__ int   ticket;

    int tid = threadIdx.x;
    int wid = tid >> 5, lane = tid & 31;
    const int mycol = tid + 1;
    const double DINF = (double)INFINITY;

    // ---- stage cost tile into smem (float4) ----
    {
        const float4* gc = (const float4*)(g_cost + (size_t)b * Nn * Mn);
        float4* c4 = (float4*)cs;
        #pragma unroll 4
        for (int idx = tid; idx < Nn * Mn / 4; idx += Mn) c4[idx] = gc[idx];
    }
    p_sh[mycol] = 0;
    if (tid <= Nn) u_sh[tid] = 0.0;
    __syncthreads();

    double v_reg = 0.0, minv;
    bool used;
    int my_p;

    for (int i = 1; i <= Nn; i++) {
        minv = DINF;
        used = false;
        my_p = p_sh[mycol];              // stable during the path
        int j0 = 0;
        // hoisted first op of numpy's (cost - u) - v for row i
        double pre = (double)cs[(i - 1) * Mn + tid] - u_sh[i];

        while (true) {
            unsigned long long key;
            if (!used) {
                double cur = pre - v_reg;
                if (cur < minv) { minv = cur; way[mycol] = j0; }
                key = dkey(minv);
            } else {
                key = 0xFFFFFFFFFFFFFFFFull;
            }
            unsigned fk = (unsigned)(key >> 32);   // monotone top-32 of key
            int idx = mycol;
            int pv  = my_p;

            // warp stage: REDUX fast path; exact (u64,idx,pv) chain on ties
            unsigned rmin = __reduce_min_sync(FULL, fk);
            unsigned bal  = __ballot_sync(FULL, fk == rmin);
            if (__popc(bal) == 1) {
                int w = __ffs(bal) - 1;
                key = __shfl_sync(FULL, key, w);
                idx = __shfl_sync(FULL, idx, w);
                pv  = __shfl_sync(FULL, pv,  w);
            } else {
                #pragma unroll
                for (int off = 16; off; off >>= 1) {
                    unsigned long long ok = __shfl_down_sync(FULL, key, off);
                    int                oi = __shfl_down_sync(FULL, idx, off);
                    int                op = __shfl_down_sync(FULL, pv,  off);
                    if (ok < key || (ok == key && oi < idx)) {
                        key = ok; idx = oi; pv = op;
                    }
                }
                key = __shfl_sync(FULL, key, 0);
                idx = __shfl_sync(FULL, idx, 0);
                pv  = __shfl_sync(FULL, pv,  0);
            }
            if (lane == 0) { wkey[wid] = key; widx[wid] = idx; wpv[wid] = pv; }
            __syncthreads();                      // barrier 1

            // block stage: WARP 0 ONLY — 4-round shfl tree over 12 records
            // (lane order == warp order == column order -> exact tie-break)
            if (wid == 0) {
                unsigned long long k64; int ix, pz;
                if (lane < 12) { k64 = wkey[lane]; ix = widx[lane]; pz = wpv[lane]; }
                else           { k64 = 0xFFFFFFFFFFFFFFFFull; ix = 0x7fffffff; pz = 0; }
                #pragma unroll
                for (int off = 8; off; off >>= 1) {
                    unsigned long long ok = __shfl_down_sync(FULL, k64, off);
                    int                oi = __shfl_down_sync(FULL, ix,  off);
                    int                op = __shfl_down_sync(FULL, pz,  off);
                    if (ok < k64 || (ok == k64 && oi < ix)) {
                        k64 = ok; ix = oi; pz = op;
                    }
                }
                if (lane == 0) {
                    double d = dunkey(k64);       // exact f64 minv[k], once
                    finrec.x = (unsigned long long)__double_as_longlong(d);
                    finrec.y = ((unsigned long long)ix << 32) | (unsigned)pz;
                }
            }
            __syncthreads();                      // barrier 2

            ulonglong2 fr = finrec;               // one LDS.128 broadcast
            double delta = __longlong_as_double((long long)fr.x);
            int k   = (int)(fr.y >> 32);
            int k_p = (int)(fr.y & 0xFFFFFFFFull);

            // prefetch NEXT step's row + u and hoist the first subtraction.
            // Safe: rows updated below (rows of used cols + row i) are all
            // distinct from k_p (row matched to the still-free column k).
            int rowbase = (k_p > 0) ? (k_p - 1) * Mn : 0;
            float  c_next = cs[rowbase + tid];
            double u_next = u_sh[(k_p > 0) ? k_p : 0];
            double pre_next = (double)c_next - u_next;   // overlaps updates

            // dual updates (numpy f64 op order; rows disjoint across threads)
            if (used) {
                v_reg -= delta;
                u_sh[my_p] += delta;
            } else {
                minv -= delta;
            }
            if (tid == 0) u_sh[i] += delta;       // virtual column 0 (p[0]=i)

            // numpy marks used[j0] at next-iteration top == mark k here
            if (mycol == k) used = true;

            j0 = k; pre = pre_next;
            if (k_p == 0) break;
        }

        // augment along alternating path (thread 0; way[] visible via BAR)
        if (tid == 0) {
            int jj = j0;
            while (jj) {
                int j1 = way[jj];
                p_sh[jj] = (j1 == 0) ? i : p_sh[j1];
                jj = j1;
            }
        }
        __syncthreads();
    }

    // ---- write assignment (direct to out for mode 0) + inverse map ----
    {
        int pi = p_sh[mycol];
        if (pi > 0) {
            int a = mycol - 1;
            g_assign[b * Nn + (pi - 1)] = a;
            a_sh[pi - 1] = a;
            if (mode == 0)      out[1 + b * Nn + (pi - 1)] = (float)a;
            else if (mode == 1) out[b * Nn + (pi - 1)]     = (float)a;
        }
    }
    __syncthreads();

    // ---- fused per-batch loss ----
    float s_ce = 0.0f, s_bl = 0.0f, s_mk = 0.0f;
    if (tid < Nn) {
        int n  = tid;
        int a  = a_sh[n];
        int tc = targ_cat[b * Nn + n];
        float2 st = g_stats[b * Mn + a];
        float logit = pred_cat[((size_t)(b * Mn + a)) * Cn + tc];
        s_ce = -(logit - st.x - logf(st.y));
        float bl = bbox_pair_cost(g_pxy[b * Mn + a], g_txy[b * Nn + n]);
        s_mk = (tc != 0) ? 1.0f : 0.0f;
        s_bl = bl * s_mk;
    }
    #pragma unroll
    for (int off = 16; off; off >>= 1) {
        s_ce += __shfl_down_sync(FULL, s_ce, off);
        s_bl += __shfl_down_sync(FULL, s_bl, off);
        s_mk += __shfl_down_sync(FULL, s_mk, off);
    }
    if (wid < 4 && lane == 0) { r1[wid] = s_ce; r2[wid] = s_bl; r3[wid] = s_mk; }
    __syncthreads();
    if (tid == 0) {
        float ce_sum = r1[0] + r1[1] + r1[2] + r1[3];
        float bl_sum = r2[0] + r2[1] + r2[2] + r2[3];
        float mk_sum = r3[0] + r3[1] + r3[2] + r3[3];
        g_loss[b] = (ce_sum / (float)Nn) + bl_sum / (mk_sum + kEPS);
        __threadfence();
        ticket = atomicAdd(&g_done, 1);
    }
    __syncthreads();

    // last-arriving block reduces the 32 losses (fixed order: deterministic)
    if (tid == 0 && ticket == Bn - 1 && (mode == 0 || mode == 2)) {
        __threadfence();
        float s = 0.0f;
        for (int bb = 0; bb < Bn; bb++) s += g_loss[bb];
        out[0] = s / (float)Bn;
    }
}

// ---------------------------------------------------------------------------
// Finalize (only for fallback modes; mode 0 handled in-solver)
// ---------------------------------------------------------------------------
__global__ void finalize_kernel(float* __restrict__ out, int mode) {
    int t = blockIdx.x * blockDim.x + threadIdx.x;
    if (mode == 1) {
        if (t < Bn * Nn) out[t] = (float)g_assign[t];
    } else {
        if (t == 0) {
            float s = 0.0f;
            for (int b = 0; b < Bn; b++) s += g_loss[b];
            out[0] = s / (float)Bn;
        }
    }
}

// ---------------------------------------------------------------------------
extern "C" void kernel_launch(void* const* d_in, const int* in_sizes, int n_in,
                              void* d_out, int out_size) {
    const float* pred_cat  = (const float*)d_in[0];
    const float* pred_bbox = (const float*)d_in[1];
    const int*   targ_cat  = (const int*)d_in[2];
    const float* targ_bbox = (const float*)d_in[3];
    float* out = (float*)d_out;

    int mode;
    if (out_size == Bn * Nn + 1)      mode = 0;
    else if (out_size == Bn * Nn)     mode = 1;
    else                              mode = 2;

    int tot = Bn * Mn + Bn * Nn;
    prep_kernel<<<(tot + 127) / 128, 128>>>(pred_cat, pred_bbox, targ_bbox);

    dim3 gc(Nn, Bn);
    cost_kernel<<<gc, Mn>>>(pred_cat, targ_cat);

    cudaFuncSetAttribute(hungarian_kernel,
                         cudaFuncAttributeMaxDynamicSharedMemorySize, SMEM_TOTAL);
    hungarian_kernel<<<Bn, Mn, SMEM_TOTAL>>>(pred_cat, targ_cat, out, mode);

    if (mode != 0)
        finalize_kernel<<<(Bn * Nn + 127) / 128, 128>>>(out, mode);
}

// round 14
// speedup vs baseline: 1.8477x; 1.1536x over previous
#include <cuda_runtime.h>
#include <math.h>
#include <float.h>
#include <stdint.h>

// Problem constants
#define Bn 32
#define Mn 384
#define Nn 128
#define Cn 92

static __device__ __constant__ float kCOST_IOU = 2.0f;
static __device__ __constant__ float kCOST_L1  = 5.0f;
static __device__ __constant__ float kCOST_CAT = 1.0f;
static __device__ __constant__ float kEPS      = 1e-7f;

// Scratch (device globals: allocation-free)
__device__ float  g_cost[(size_t)Bn * Nn * Mn];   // [b][n][m]
__device__ float2 g_stats[Bn * Mn];               // (max, sumexp) per (b,m)
__device__ float4 g_pxy[Bn * Mn];                 // pred xyxy
__device__ float4 g_txy[Bn * Nn];                 // targ xyxy
__device__ int    g_assign[Bn * Nn];
__device__ float  g_loss[Bn];
__device__ int    g_done;

// ---------------------------------------------------------------------------
// Kernel 1: per-(b,m) softmax stats + pred xyxy; per-(b,n) targ xyxy
// ---------------------------------------------------------------------------
__global__ void prep_kernel(const float* __restrict__ pred_cat,
                            const float* __restrict__ pred_bbox,
                            const float* __restrict__ targ_bbox) {
    int t = blockIdx.x * blockDim.x + threadIdx.x;
    if (t == 0) g_done = 0;                      // reset ticket each replay
    if (t < Bn * Mn) {
        const float4* r4 = (const float4*)(pred_cat + (size_t)t * Cn);
        float mx = -FLT_MAX;
        #pragma unroll
        for (int q = 0; q < Cn / 4; q++) {
            float4 v = r4[q];
            mx = fmaxf(mx, v.x); mx = fmaxf(mx, v.y);
            mx = fmaxf(mx, v.z); mx = fmaxf(mx, v.w);
        }
        float s = 0.0f;
        #pragma unroll
        for (int q = 0; q < Cn / 4; q++) {
            float4 v = r4[q];
            s += expf(v.x - mx); s += expf(v.y - mx);
            s += expf(v.z - mx); s += expf(v.w - mx);
        }
        g_stats[t] = make_float2(mx, s);
        const float* pb = pred_bbox + (size_t)t * 4;
        float cx = pb[0], cy = pb[1], w = pb[2], h = pb[3];
        g_pxy[t] = make_float4(cx - 0.5f * w, cy - 0.5f * h,
                               cx + 0.5f * w, cy + 0.5f * h);
    } else if (t < Bn * Mn + Bn * Nn) {
        int u = t - Bn * Mn;
        float cx = targ_bbox[u * 4 + 0], cy = targ_bbox[u * 4 + 1];
        float w  = targ_bbox[u * 4 + 2], h  = targ_bbox[u * 4 + 3];
        g_txy[u] = make_float4(cx - 0.5f * w, cy - 0.5f * h,
                               cx + 0.5f * w, cy + 0.5f * h);
    }
}

// GIoU-loss + L1 helper (matches reference formula order)
__device__ __forceinline__ float bbox_pair_cost(float4 p, float4 t) {
    float ix1 = fmaxf(p.x, t.x), iy1 = fmaxf(p.y, t.y);
    float ix2 = fminf(p.z, t.z), iy2 = fminf(p.w, t.w);
    float inter = fmaxf(ix2 - ix1, 0.0f) * fmaxf(iy2 - iy1, 0.0f);
    float ap = (p.z - p.x) * (p.w - p.y);
    float at = (t.z - t.x) * (t.w - t.y);
    float un = ap + at - inter;
    float iou = inter / (un + kEPS);
    float cx1 = fminf(p.x, t.x), cy1 = fminf(p.y, t.y);
    float cx2 = fmaxf(p.z, t.z), cy2 = fmaxf(p.w, t.w);
    float ac = (cx2 - cx1) * (cy2 - cy1);
    float giou = iou - (ac - un) / (ac + kEPS);
    float gl = 1.0f - giou;
    float l1 = (fabsf(p.x - t.x) + fabsf(p.y - t.y) +
                fabsf(p.z - t.z) + fabsf(p.w - t.w)) * 0.25f;
    return kCOST_IOU * gl + kCOST_L1 * l1;
}

// ---------------------------------------------------------------------------
// Kernel 2: cost matrix, one block per (b,n), thread per m (coalesced writes)
// ---------------------------------------------------------------------------
__global__ __launch_bounds__(Mn) void cost_kernel(const float* __restrict__ pred_cat,
                                                  const int* __restrict__ targ_cat) {
    int b = blockIdx.y, n = blockIdx.x, m = threadIdx.x;
    int tc = targ_cat[b * Nn + n];
    float4 t4 = g_txy[b * Nn + n];
    float maskf = (tc != 0) ? 1.0f : 0.0f;

    float2 st = g_stats[b * Mn + m];
    float logit = pred_cat[((size_t)(b * Mn + m)) * Cn + tc];
    float prob = expf(logit - st.x) / st.y;
    float cat = kCOST_CAT * (1.0f - prob);

    float bb = bbox_pair_cost(g_pxy[b * Mn + m], t4);
    g_cost[((size_t)(b * Nn + n)) * Mn + m] = cat + bb * maskf;
}

// ---------------------------------------------------------------------------
// Kernel 3: Hungarian (JV) — block-per-batch, 384 threads, 1 col/thread.
// Issue-bound solver. Winner-writes-direct min selection at BOTH stages:
// REDUX(top-32)+ballot picks a unique winner who stores its OWN record (no
// shfl broadcasts); rare exact ties resolved by a 2nd REDUX on the low-32 +
// lowest-lane rule (lane order == column order -> numpy tie-break exact).
// f64 duals, numpy op order.
// ---------------------------------------------------------------------------
#define CS_BYTES   (Nn * Mn * 4)             // 196608
#define OFF_U      (CS_BYTES)                // double[Nn+1]
#define OFF_P      (OFF_U + (Nn + 1) * 8)    // int[Mn+1]
#define OFF_WAY    (OFF_P + (Mn + 1) * 4)    // int[Mn+1]
#define SMEM_TOTAL (OFF_WAY + (Mn + 1) * 4)  // ~200 KB dynamic

__device__ __forceinline__ unsigned long long dkey(double d) {
    unsigned long long b = (unsigned long long)__double_as_longlong(d);
    return (b & 0x8000000000000000ull) ? ~b : (b | 0x8000000000000000ull);
}
__device__ __forceinline__ double dunkey(unsigned long long k) {
    unsigned long long b = (k & 0x8000000000000000ull)
                         ? (k & 0x7FFFFFFFFFFFFFFFull) : ~k;
    return __longlong_as_double((long long)b);
}

__global__ __launch_bounds__(Mn, 1) void hungarian_kernel(
        const float* __restrict__ pred_cat,
        const int* __restrict__ targ_cat,
        float* __restrict__ out, int mode) {
    const unsigned FULL = 0xffffffffu;
    int b = blockIdx.x;
    extern __shared__ unsigned char smem[];
    float*  cs   = (float*)smem;
    double* u_sh = (double*)(smem + OFF_U);
    int*    p_sh = (int*)(smem + OFF_P);
    int*    way  = (int*)(smem + OFF_WAY);

    __shared__ unsigned long long wkey[12];
    __shared__ int widx[12];
    __shared__ int wpv [12];
    __shared__ ulonglong2 finrec;        // {delta_bits, k<<32|k_p}
    __shared__ int   a_sh[Nn];
    __shared__ float r1[4], r2[4], r3[4];
    __shared__ int   ticket;

    int tid = threadIdx.x;
    int wid = tid >> 5, lane = tid & 31;
    const int mycol = tid + 1;
    const double DINF = (double)INFINITY;

    // ---- stage cost tile into smem (float4) ----
    {
        const float4* gc = (const float4*)(g_cost + (size_t)b * Nn * Mn);
        float4* c4 = (float4*)cs;
        #pragma unroll 4
        for (int idx = tid; idx < Nn * Mn / 4; idx += Mn) c4[idx] = gc[idx];
    }
    p_sh[mycol] = 0;
    if (tid <= Nn) u_sh[tid] = 0.0;
    __syncthreads();

    double v_reg = 0.0, minv;
    bool used;
    int my_p;

    for (int i = 1; i <= Nn; i++) {
        minv = DINF;
        used = false;
        my_p = p_sh[mycol];              // stable during the path
        int j0 = 0;
        // hoisted first op of numpy's (cost - u) - v for row i
        double pre = (double)cs[(i - 1) * Mn + tid] - u_sh[i];

        while (true) {
            unsigned long long key;
            if (!used) {
                double cur = pre - v_reg;
                if (cur < minv) { minv = cur; way[mycol] = j0; }
                key = dkey(minv);
            } else {
                key = 0xFFFFFFFFFFFFFFFFull;
            }
            unsigned fk = (unsigned)(key >> 32);   // monotone top-32 of key

            // warp stage: winner writes its OWN record (no shfl broadcast).
            // Unique top-32 min -> that lane holds the exact u64 min.
            // Tie -> 2nd REDUX on low-32; lowest lane (= lowest column) wins.
            {
                unsigned rhi = __reduce_min_sync(FULL, fk);
                unsigned bal = __ballot_sync(FULL, fk == rhi);
                bool win;
                if (__popc(bal) == 1) {            // warp-uniform branch
                    win = (fk == rhi);
                } else {
                    unsigned cand = (fk == rhi) ? (unsigned)key : 0xFFFFFFFFu;
                    unsigned rlo  = __reduce_min_sync(FULL, cand);
                    unsigned bal2 = __ballot_sync(FULL,
                                        (fk == rhi) & (cand == rlo));
                    win = (lane == __ffs(bal2) - 1);
                }
                if (win) { wkey[wid] = key; widx[wid] = mycol; wpv[wid] = my_p; }
            }
            __syncthreads();                      // barrier 1

            // block stage: WARP 0 ONLY — REDUX over the 12 records.
            // Warp order == column-block order -> lowest lane = lowest column.
            if (wid == 0) {
                unsigned long long k64; int ix, pz;
                if (lane < 12) { k64 = wkey[lane]; ix = widx[lane]; pz = wpv[lane]; }
                else           { k64 = 0xFFFFFFFFFFFFFFFFull; ix = 0x7fffffff; pz = 0; }
                unsigned hi2  = (unsigned)(k64 >> 32);
                unsigned rhi2 = __reduce_min_sync(FULL, hi2);
                unsigned b2   = __ballot_sync(FULL, hi2 == rhi2);
                bool w2;
                if (__popc(b2) == 1) {
                    w2 = (hi2 == rhi2);
                } else {
                    unsigned cand2 = (hi2 == rhi2) ? (unsigned)k64 : 0xFFFFFFFFu;
                    unsigned rlo2  = __reduce_min_sync(FULL, cand2);
                    unsigned b3    = __ballot_sync(FULL,
                                        (hi2 == rhi2) & (cand2 == rlo2));
                    w2 = (lane == __ffs(b3) - 1);
                }
                if (w2) {
                    double d = dunkey(k64);       // exact f64 minv[k], once
                    finrec.x = (unsigned long long)__double_as_longlong(d);
                    finrec.y = ((unsigned long long)ix << 32) | (unsigned)pz;
                }
            }
            __syncthreads();                      // barrier 2

            ulonglong2 fr = finrec;               // one LDS.128 broadcast
            double delta = __longlong_as_double((long long)fr.x);
            int k   = (int)(fr.y >> 32);
            int k_p = (int)(fr.y & 0xFFFFFFFFull);

            // prefetch NEXT step's row + u and hoist the first subtraction.
            // Safe: rows updated below (rows of used cols + row i) are all
            // distinct from k_p (row matched to the still-free column k).
            int rowbase = (k_p > 0) ? (k_p - 1) * Mn : 0;
            float  c_next = cs[rowbase + tid];
            double u_next = u_sh[(k_p > 0) ? k_p : 0];
            double pre_next = (double)c_next - u_next;   // overlaps updates

            // dual updates (numpy f64 op order; rows disjoint across threads)
            if (used) {
                v_reg -= delta;
                u_sh[my_p] += delta;
            } else {
                minv -= delta;
            }
            if (tid == 0) u_sh[i] += delta;       // virtual column 0 (p[0]=i)

            // numpy marks used[j0] at next-iteration top == mark k here
            if (mycol == k) used = true;

            j0 = k; pre = pre_next;
            if (k_p == 0) break;
        }

        // augment along alternating path (thread 0; way[] visible via BAR)
        if (tid == 0) {
            int jj = j0;
            while (jj) {
                int j1 = way[jj];
                p_sh[jj] = (j1 == 0) ? i : p_sh[j1];
                jj = j1;
            }
        }
        __syncthreads();
    }

    // ---- write assignment (direct to out for mode 0) + inverse map ----
    {
        int pi = p_sh[mycol];
        if (pi > 0) {
            int a = mycol - 1;
            g_assign[b * Nn + (pi - 1)] = a;
            a_sh[pi - 1] = a;
            if (mode == 0)      out[1 + b * Nn + (pi - 1)] = (float)a;
            else if (mode == 1) out[b * Nn + (pi - 1)]     = (float)a;
        }
    }
    __syncthreads();

    // ---- fused per-batch loss ----
    float s_ce = 0.0f, s_bl = 0.0f, s_mk = 0.0f;
    if (tid < Nn) {
        int n  = tid;
        int a  = a_sh[n];
        int tc = targ_cat[b * Nn + n];
        float2 st = g_stats[b * Mn + a];
        float logit = pred_cat[((size_t)(b * Mn + a)) * Cn + tc];
        s_ce = -(logit - st.x - logf(st.y));
        float bl = bbox_pair_cost(g_pxy[b * Mn + a], g_txy[b * Nn + n]);
        s_mk = (tc != 0) ? 1.0f : 0.0f;
        s_bl = bl * s_mk;
    }
    #pragma unroll
    for (int off = 16; off; off >>= 1) {
        s_ce += __shfl_down_sync(FULL, s_ce, off);
        s_bl += __shfl_down_sync(FULL, s_bl, off);
        s_mk += __shfl_down_sync(FULL, s_mk, off);
    }
    if (wid < 4 && lane == 0) { r1[wid] = s_ce; r2[wid] = s_bl; r3[wid] = s_mk; }
    __syncthreads();
    if (tid == 0) {
        float ce_sum = r1[0] + r1[1] + r1[2] + r1[3];
        float bl_sum = r2[0] + r2[1] + r2[2] + r2[3];
        float mk_sum = r3[0] + r3[1] + r3[2] + r3[3];
        g_loss[b] = (ce_sum / (float)Nn) + bl_sum / (mk_sum + kEPS);
        __threadfence();
        ticket = atomicAdd(&g_done, 1);
    }
    __syncthreads();

    // last-arriving block reduces the 32 losses (fixed order: deterministic)
    if (tid == 0 && ticket == Bn - 1 && (mode == 0 || mode == 2)) {
        __threadfence();
        float s = 0.0f;
        for (int bb = 0; bb < Bn; bb++) s += g_loss[bb];
        out[0] = s / (float)Bn;
    }
}

// ---------------------------------------------------------------------------
// Finalize (only for fallback modes; mode 0 handled in-solver)
// ---------------------------------------------------------------------------
__global__ void finalize_kernel(float* __restrict__ out, int mode) {
    int t = blockIdx.x * blockDim.x + threadIdx.x;
    if (mode == 1) {
        if (t < Bn * Nn) out[t] = (float)g_assign[t];
    } else {
        if (t == 0) {
            float s = 0.0f;
            for (int b = 0; b < Bn; b++) s += g_loss[b];
            out[0] = s / (float)Bn;
        }
    }
}

// ---------------------------------------------------------------------------
extern "C" void kernel_launch(void* const* d_in, const int* in_sizes, int n_in,
                              void* d_out, int out_size) {
    const float* pred_cat  = (const float*)d_in[0];
    const float* pred_bbox = (const float*)d_in[1];
    const int*   targ_cat  = (const int*)d_in[2];
    const float* targ_bbox = (const float*)d_in[3];
    float* out = (float*)d_out;

    int mode;
    if (out_size == Bn * Nn + 1)      mode = 0;
    else if (out_size == Bn * Nn)     mode = 1;
    else                              mode = 2;

    int tot = Bn * Mn + Bn * Nn;
    prep_kernel<<<(tot + 127) / 128, 128>>>(pred_cat, pred_bbox, targ_bbox);

    dim3 gc(Nn, Bn);
    cost_kernel<<<gc, Mn>>>(pred_cat, targ_cat);

    cudaFuncSetAttribute(hungarian_kernel,
                         cudaFuncAttributeMaxDynamicSharedMemorySize, SMEM_TOTAL);
    hungarian_kernel<<<Bn, Mn, SMEM_TOTAL>>>(pred_cat, targ_cat, out, mode);

    if (mode != 0)
        finalize_kernel<<<(Bn * Nn + 127) / 128, 128>>>(out, mode);
}

// round 15
// speedup vs baseline: 2.0176x; 1.0920x over previous
#include <cuda_runtime.h>
#include <math.h>
#include <float.h>
#include <stdint.h>

// Problem constants
#define Bn 32
#define Mn 384
#define Nn 128
#define Cn 92

static __device__ __constant__ float kCOST_IOU = 2.0f;
static __device__ __constant__ float kCOST_L1  = 5.0f;
static __device__ __constant__ float kCOST_CAT = 1.0f;
static __device__ __constant__ float kEPS      = 1e-7f;

// Scratch (device globals: allocation-free)
__device__ float  g_cost[(size_t)Bn * Nn * Mn];   // [b][n][m]
__device__ float2 g_stats[Bn * Mn];               // (max, sumexp) per (b,m)
__device__ float4 g_pxy[Bn * Mn];                 // pred xyxy
__device__ float4 g_txy[Bn * Nn];                 // targ xyxy
__device__ int    g_assign[Bn * Nn];
__device__ float  g_loss[Bn];
__device__ int    g_done;

// ---------------------------------------------------------------------------
// Kernel 1: per-(b,m) softmax stats + pred xyxy; per-(b,n) targ xyxy
// ---------------------------------------------------------------------------
__global__ void prep_kernel(const float* __restrict__ pred_cat,
                            const float* __restrict__ pred_bbox,
                            const float* __restrict__ targ_bbox) {
    int t = blockIdx.x * blockDim.x + threadIdx.x;
    if (t == 0) g_done = 0;                      // reset ticket each replay
    if (t < Bn * Mn) {
        const float4* r4 = (const float4*)(pred_cat + (size_t)t * Cn);
        float mx = -FLT_MAX;
        #pragma unroll
        for (int q = 0; q < Cn / 4; q++) {
            float4 v = r4[q];
            mx = fmaxf(mx, v.x); mx = fmaxf(mx, v.y);
            mx = fmaxf(mx, v.z); mx = fmaxf(mx, v.w);
        }
        float s = 0.0f;
        #pragma unroll
        for (int q = 0; q < Cn / 4; q++) {
            float4 v = r4[q];
            s += expf(v.x - mx); s += expf(v.y - mx);
            s += expf(v.z - mx); s += expf(v.w - mx);
        }
        g_stats[t] = make_float2(mx, s);
        const float* pb = pred_bbox + (size_t)t * 4;
        float cx = pb[0], cy = pb[1], w = pb[2], h = pb[3];
        g_pxy[t] = make_float4(cx - 0.5f * w, cy - 0.5f * h,
                               cx + 0.5f * w, cy + 0.5f * h);
    } else if (t < Bn * Mn + Bn * Nn) {
        int u = t - Bn * Mn;
        float cx = targ_bbox[u * 4 + 0], cy = targ_bbox[u * 4 + 1];
        float w  = targ_bbox[u * 4 + 2], h  = targ_bbox[u * 4 + 3];
        g_txy[u] = make_float4(cx - 0.5f * w, cy - 0.5f * h,
                               cx + 0.5f * w, cy + 0.5f * h);
    }
}

// GIoU-loss + L1 helper (matches reference formula order)
__device__ __forceinline__ float bbox_pair_cost(float4 p, float4 t) {
    float ix1 = fmaxf(p.x, t.x), iy1 = fmaxf(p.y, t.y);
    float ix2 = fminf(p.z, t.z), iy2 = fminf(p.w, t.w);
    float inter = fmaxf(ix2 - ix1, 0.0f) * fmaxf(iy2 - iy1, 0.0f);
    float ap = (p.z - p.x) * (p.w - p.y);
    float at = (t.z - t.x) * (t.w - t.y);
    float un = ap + at - inter;
    float iou = inter / (un + kEPS);
    float cx1 = fminf(p.x, t.x), cy1 = fminf(p.y, t.y);
    float cx2 = fmaxf(p.z, t.z), cy2 = fmaxf(p.w, t.w);
    float ac = (cx2 - cx1) * (cy2 - cy1);
    float giou = iou - (ac - un) / (ac + kEPS);
    float gl = 1.0f - giou;
    float l1 = (fabsf(p.x - t.x) + fabsf(p.y - t.y) +
                fabsf(p.z - t.z) + fabsf(p.w - t.w)) * 0.25f;
    return kCOST_IOU * gl + kCOST_L1 * l1;
}

// ---------------------------------------------------------------------------
// Kernel 2: cost matrix, one block per (b,n), thread per m (coalesced writes)
// ---------------------------------------------------------------------------
__global__ __launch_bounds__(Mn) void cost_kernel(const float* __restrict__ pred_cat,
                                                  const int* __restrict__ targ_cat) {
    int b = blockIdx.y, n = blockIdx.x, m = threadIdx.x;
    int tc = targ_cat[b * Nn + n];
    float4 t4 = g_txy[b * Nn + n];
    float maskf = (tc != 0) ? 1.0f : 0.0f;

    float2 st = g_stats[b * Mn + m];
    float logit = pred_cat[((size_t)(b * Mn + m)) * Cn + tc];
    float prob = expf(logit - st.x) / st.y;
    float cat = kCOST_CAT * (1.0f - prob);

    float bb = bbox_pair_cost(g_pxy[b * Mn + m], t4);
    g_cost[((size_t)(b * Nn + n)) * Mn + m] = cat + bb * maskf;
}

// ---------------------------------------------------------------------------
// Kernel 3: Hungarian (JV) — block-per-batch, 384 threads, 1 col/thread.
// ONE barrier per step. Warp stage: winner-writes-direct (REDUX + ballot;
// rare hi-tie -> 2nd REDUX on low-32, lowest lane = lowest column). Block
// stage: EVERY warp reduces the 12 staged records with the same REDUX
// pattern + 3 shfl broadcasts from the winner lane (record order = column-
// block order -> numpy lowest-index tie-break exact). Staging arrays are
// parity double-buffered (WAR safety with a single barrier).
// f64 duals, numpy op order.
// ---------------------------------------------------------------------------
#define CS_BYTES   (Nn * Mn * 4)             // 196608
#define OFF_U      (CS_BYTES)                // double[Nn+1]
#define OFF_P      (OFF_U + (Nn + 1) * 8)    // int[Mn+1]
#define OFF_WAY    (OFF_P + (Mn + 1) * 4)    // int[Mn+1]
#define SMEM_TOTAL (OFF_WAY + (Mn + 1) * 4)  // ~200 KB dynamic

__device__ __forceinline__ unsigned long long dkey(double d) {
    unsigned long long b = (unsigned long long)__double_as_longlong(d);
    return (b & 0x8000000000000000ull) ? ~b : (b | 0x8000000000000000ull);
}
__device__ __forceinline__ double dunkey(unsigned long long k) {
    unsigned long long b = (k & 0x8000000000000000ull)
                         ? (k & 0x7FFFFFFFFFFFFFFFull) : ~k;
    return __longlong_as_double((long long)b);
}

__global__ __launch_bounds__(Mn, 1) void hungarian_kernel(
        const float* __restrict__ pred_cat,
        const int* __restrict__ targ_cat,
        float* __restrict__ out, int mode) {
    const unsigned FULL = 0xffffffffu;
    int b = blockIdx.x;
    extern __shared__ unsigned char smem[];
    float*  cs   = (float*)smem;
    double* u_sh = (double*)(smem + OFF_U);
    int*    p_sh = (int*)(smem + OFF_P);
    int*    way  = (int*)(smem + OFF_WAY);

    __shared__ unsigned long long wkey[2][12];
    __shared__ int widx[2][12];
    __shared__ int wpv [2][12];
    __shared__ int   a_sh[Nn];
    __shared__ float r1[4], r2[4], r3[4];
    __shared__ int   ticket;

    int tid = threadIdx.x;
    int wid = tid >> 5, lane = tid & 31;
    const int mycol = tid + 1;
    const double DINF = (double)INFINITY;

    // ---- stage cost tile into smem (float4) ----
    {
        const float4* gc = (const float4*)(g_cost + (size_t)b * Nn * Mn);
        float4* c4 = (float4*)cs;
        #pragma unroll 4
        for (int idx = tid; idx < Nn * Mn / 4; idx += Mn) c4[idx] = gc[idx];
    }
    p_sh[mycol] = 0;
    if (tid <= Nn) u_sh[tid] = 0.0;
    __syncthreads();

    double v_reg = 0.0, minv;
    bool used;
    int my_p;
    int parity = 0;

    for (int i = 1; i <= Nn; i++) {
        minv = DINF;
        used = false;
        my_p = p_sh[mycol];              // stable during the path
        int j0 = 0;
        // hoisted first op of numpy's (cost - u) - v for row i
        double pre = (double)cs[(i - 1) * Mn + tid] - u_sh[i];

        while (true) {
            unsigned long long key;
            if (!used) {
                double cur = pre - v_reg;
                if (cur < minv) { minv = cur; way[mycol] = j0; }
                key = dkey(minv);
            } else {
                key = 0xFFFFFFFFFFFFFFFFull;
            }
            unsigned fk = (unsigned)(key >> 32);   // monotone top-32 of key

            // warp stage: winner writes its OWN record (no broadcasts)
            {
                unsigned rhi = __reduce_min_sync(FULL, fk);
                unsigned bal = __ballot_sync(FULL, fk == rhi);
                bool win;
                if (__popc(bal) == 1) {            // warp-uniform branch
                    win = (fk == rhi);
                } else {
                    unsigned cand = (fk == rhi) ? (unsigned)key : 0xFFFFFFFFu;
                    unsigned rlo  = __reduce_min_sync(FULL, cand);
                    unsigned bal2 = __ballot_sync(FULL,
                                        (fk == rhi) & (cand == rlo));
                    win = (lane == __ffs(bal2) - 1);
                }
                if (win) {
                    wkey[parity][wid] = key;
                    widx[parity][wid] = mycol;
                    wpv [parity][wid] = my_p;
                }
            }
            __syncthreads();                      // the ONLY barrier per step

            // block stage: EVERY warp reduces the 12 records (REDUX + shfl)
            double delta; int k, k_p;
            {
                unsigned long long k64; int ix, pz;
                if (lane < 12) {
                    k64 = wkey[parity][lane];
                    ix  = widx[parity][lane];
                    pz  = wpv [parity][lane];
                } else {
                    k64 = 0xFFFFFFFFFFFFFFFFull; ix = 0x7fffffff; pz = 0;
                }
                unsigned hi2  = (unsigned)(k64 >> 32);
                unsigned rhi2 = __reduce_min_sync(FULL, hi2);
                unsigned b2   = __ballot_sync(FULL, hi2 == rhi2);
                int wlane;
                if (__popc(b2) == 1) {
                    wlane = __ffs(b2) - 1;
                } else {
                    unsigned cand2 = (hi2 == rhi2) ? (unsigned)k64 : 0xFFFFFFFFu;
                    unsigned rlo2  = __reduce_min_sync(FULL, cand2);
                    unsigned b3    = __ballot_sync(FULL,
                                        (hi2 == rhi2) & (cand2 == rlo2));
                    wlane = __ffs(b3) - 1;        // lowest lane = lowest column
                }
                unsigned long long kk = __shfl_sync(FULL, k64, wlane);
                k   = __shfl_sync(FULL, ix, wlane);
                k_p = __shfl_sync(FULL, pz, wlane);
                delta = dunkey(kk);               // exact f64 minv[k]
            }

            // prefetch NEXT step's row + u and hoist the first subtraction.
            // Safe: rows updated below (rows of used cols + row i) are all
            // distinct from k_p (row matched to the still-free column k).
            int rowbase = (k_p > 0) ? (k_p - 1) * Mn : 0;
            float  c_next = cs[rowbase + tid];
            double u_next = u_sh[(k_p > 0) ? k_p : 0];
            double pre_next = (double)c_next - u_next;   // overlaps updates

            // dual updates (numpy f64 op order; rows disjoint across threads)
            if (used) {
                v_reg -= delta;
                u_sh[my_p] += delta;
            } else {
                minv -= delta;
            }
            if (tid == 0) u_sh[i] += delta;       // virtual column 0 (p[0]=i)

            // numpy marks used[j0] at next-iteration top == mark k here
            if (mycol == k) used = true;

            parity ^= 1;
            j0 = k; pre = pre_next;
            if (k_p == 0) break;
        }

        // augment along alternating path (thread 0; way[] visible via BAR)
        if (tid == 0) {
            int jj = j0;
            while (jj) {
                int j1 = way[jj];
                p_sh[jj] = (j1 == 0) ? i : p_sh[j1];
                jj = j1;
            }
        }
        __syncthreads();
    }

    // ---- write assignment (direct to out for mode 0) + inverse map ----
    {
        int pi = p_sh[mycol];
        if (pi > 0) {
            int a = mycol - 1;
            g_assign[b * Nn + (pi - 1)] = a;
            a_sh[pi - 1] = a;
            if (mode == 0)      out[1 + b * Nn + (pi - 1)] = (float)a;
            else if (mode == 1) out[b * Nn + (pi - 1)]     = (float)a;
        }
    }
    __syncthreads();

    // ---- fused per-batch loss ----
    float s_ce = 0.0f, s_bl = 0.0f, s_mk = 0.0f;
    if (tid < Nn) {
        int n  = tid;
        int a  = a_sh[n];
        int tc = targ_cat[b * Nn + n];
        float2 st = g_stats[b * Mn + a];
        float logit = pred_cat[((size_t)(b * Mn + a)) * Cn + tc];
        s_ce = -(logit - st.x - logf(st.y));
        float bl = bbox_pair_cost(g_pxy[b * Mn + a], g_txy[b * Nn + n]);
        s_mk = (tc != 0) ? 1.0f : 0.0f;
        s_bl = bl * s_mk;
    }
    #pragma unroll
    for (int off = 16; off; off >>= 1) {
        s_ce += __shfl_down_sync(FULL, s_ce, off);
        s_bl += __shfl_down_sync(FULL, s_bl, off);
        s_mk += __shfl_down_sync(FULL, s_mk, off);
    }
    if (wid < 4 && lane == 0) { r1[wid] = s_ce; r2[wid] = s_bl; r3[wid] = s_mk; }
    __syncthreads();
    if (tid == 0) {
        float ce_sum = r1[0] + r1[1] + r1[2] + r1[3];
        float bl_sum = r2[0] + r2[1] + r2[2] + r2[3];
        float mk_sum = r3[0] + r3[1] + r3[2] + r3[3];
        g_loss[b] = (ce_sum / (float)Nn) + bl_sum / (mk_sum + kEPS);
        __threadfence();
        ticket = atomicAdd(&g_done, 1);
    }
    __syncthreads();

    // last-arriving block reduces the 32 losses (fixed order: deterministic)
    if (tid == 0 && ticket == Bn - 1 && (mode == 0 || mode == 2)) {
        __threadfence();
        float s = 0.0f;
        for (int bb = 0; bb < Bn; bb++) s += g_loss[bb];
        out[0] = s / (float)Bn;
    }
}

// ---------------------------------------------------------------------------
// Finalize (only for fallback modes; mode 0 handled in-solver)
// ---------------------------------------------------------------------------
__global__ void finalize_kernel(float* __restrict__ out, int mode) {
    int t = blockIdx.x * blockDim.x + threadIdx.x;
    if (mode == 1) {
        if (t < Bn * Nn) out[t] = (float)g_assign[t];
    } else {
        if (t == 0) {
            float s = 0.0f;
            for (int b = 0; b < Bn; b++) s += g_loss[b];
            out[0] = s / (float)Bn;
        }
    }
}

// ---------------------------------------------------------------------------
extern "C" void kernel_launch(void* const* d_in, const int* in_sizes, int n_in,
                              void* d_out, int out_size) {
    const float* pred_cat  = (const float*)d_in[0];
    const float* pred_bbox = (const float*)d_in[1];
    const int*   targ_cat  = (const int*)d_in[2];
    const float* targ_bbox = (const float*)d_in[3];
    float* out = (float*)d_out;

    int mode;
    if (out_size == Bn * Nn + 1)      mode = 0;
    else if (out_size == Bn * Nn)     mode = 1;
    else                              mode = 2;

    int tot = Bn * Mn + Bn * Nn;
    prep_kernel<<<(tot + 127) / 128, 128>>>(pred_cat, pred_bbox, targ_bbox);

    dim3 gc(Nn, Bn);
    cost_kernel<<<gc, Mn>>>(pred_cat, targ_cat);

    cudaFuncSetAttribute(hungarian_kernel,
                         cudaFuncAttributeMaxDynamicSharedMemorySize, SMEM_TOTAL);
    hungarian_kernel<<<Bn, Mn, SMEM_TOTAL>>>(pred_cat, targ_cat, out, mode);

    if (mode != 0)
        finalize_kernel<<<(Bn * Nn + 127) / 128, 128>>>(out, mode);
}